// round 2
// baseline (speedup 1.0000x reference)
#include <cuda_runtime.h>

#define TT 64
#define BB 1024
#define II 64
#define HH 256

// Scratch: hs[t][b][h] — first holds xW+biases, then overwritten in-place by the scan.
__device__ float g_hs[(size_t)TT * BB * HH];

// ---------------------------------------------------------------------------
// Kernel 1: g_hs[t,b,h] = data[t,b,:] . W_ih[h,:] + b_ih[h] + b_hh[h]
// Each thread owns output feature h = tid, weight row cached in registers.
// ---------------------------------------------------------------------------
__global__ void __launch_bounds__(256) xw_kernel(
    const float* __restrict__ data,
    const float* __restrict__ W_ih,
    const float* __restrict__ b_ih,
    const float* __restrict__ b_hh)
{
    __shared__ float sX[256];  // 4 rows x 64 inputs
    const int tid = threadIdx.x;
    const long r0 = (long)blockIdx.x * 64;  // 64 (t,b)-rows per block

    float w[64];
    const float4* W4 = reinterpret_cast<const float4*>(W_ih) + tid * 16;
#pragma unroll
    for (int c = 0; c < 16; c++) {
        float4 v = W4[c];
        w[4*c+0] = v.x; w[4*c+1] = v.y; w[4*c+2] = v.z; w[4*c+3] = v.w;
    }
    const float bsum = b_ih[tid] + b_hh[tid];

    for (int rg = 0; rg < 16; rg++) {
        __syncthreads();
        sX[tid] = data[r0 * II + rg * 256 + tid];
        __syncthreads();
        float a0 = bsum, a1 = bsum, a2 = bsum, a3 = bsum;
        const float4* X4 = reinterpret_cast<const float4*>(sX);
#pragma unroll
        for (int c = 0; c < 16; c++) {
            float4 x;
            x = X4[c];      a0 += x.x*w[4*c] + x.y*w[4*c+1] + x.z*w[4*c+2] + x.w*w[4*c+3];
            x = X4[16+c];   a1 += x.x*w[4*c] + x.y*w[4*c+1] + x.z*w[4*c+2] + x.w*w[4*c+3];
            x = X4[32+c];   a2 += x.x*w[4*c] + x.y*w[4*c+1] + x.z*w[4*c+2] + x.w*w[4*c+3];
            x = X4[48+c];   a3 += x.x*w[4*c] + x.y*w[4*c+1] + x.z*w[4*c+2] + x.w*w[4*c+3];
        }
        long r = r0 + rg * 4;
        g_hs[(r+0)*HH + tid] = a0;
        g_hs[(r+1)*HH + tid] = a1;
        g_hs[(r+2)*HH + tid] = a2;
        g_hs[(r+3)*HH + tid] = a3;
    }
}

// ---------------------------------------------------------------------------
// Kernel 2 (launched T times): hs[t] = relu(hs[t] + hs[t-1] @ W_hh^T)
// 128 blocks: (64 b-tiles of 16) x (2 h-halves of 128).
// W slice transposed into smem Ws[k][hl] (stride 129 -> conflict free),
// hprev tile hp[bb][k] (stride 257). Thread tile: 2 b x 4 h (h strided by 32).
// ---------------------------------------------------------------------------
__global__ void __launch_bounds__(256) rnn_step_kernel(
    int t, const float* __restrict__ h0_in, const float* __restrict__ W_hh)
{
    extern __shared__ float sm[];
    float* Ws = sm;               // [256][129]
    float* hp = sm + 256 * 129;   // [16][257]
    const int tid = threadIdx.x;
    const int bt = blockIdx.x >> 1;
    const int hh = blockIdx.x & 1;
    const int b0 = bt * 16;
    const int hbase = hh * 128;

    const float* hprev = (t == 0) ? h0_in : (g_hs + (size_t)(t - 1) * BB * HH);
    float* hcur = g_hs + (size_t)t * BB * HH;

#pragma unroll 4
    for (int m = tid; m < 128 * 256; m += 256) {
        int hl = m >> 8, k = m & 255;
        Ws[k * 129 + hl] = W_hh[(size_t)(hbase + hl) * HH + k];
    }
#pragma unroll
    for (int m = tid; m < 16 * 256; m += 256) {
        int bb = m >> 8, k = m & 255;
        hp[bb * 257 + k] = hprev[(size_t)(b0 + bb) * HH + k];
    }

    const int bg = tid >> 5, hg = tid & 31;
    const int bA = b0 + bg * 2;
    const int bC = bA + 1;
    float acc0[4], acc1[4];
#pragma unroll
    for (int q = 0; q < 4; q++) {
        acc0[q] = hcur[(size_t)bA * HH + hbase + hg + 32 * q];
        acc1[q] = hcur[(size_t)bC * HH + hbase + hg + 32 * q];
    }
    __syncthreads();

    const float* hpA = hp + (bg * 2) * 257;
    const float* hpB = hpA + 257;
#pragma unroll 4
    for (int k = 0; k < 256; k++) {
        float hv0 = hpA[k];
        float hv1 = hpB[k];
        const float* wr = Ws + k * 129 + hg;
#pragma unroll
        for (int q = 0; q < 4; q++) {
            float wv = wr[32 * q];
            acc0[q] += hv0 * wv;
            acc1[q] += hv1 * wv;
        }
    }
#pragma unroll
    for (int q = 0; q < 4; q++) {
        hcur[(size_t)bA * HH + hbase + hg + 32 * q] = fmaxf(acc0[q], 0.f);
        hcur[(size_t)bC * HH + hbase + hg + 32 * q] = fmaxf(acc1[q], 0.f);
    }
}

// ---------------------------------------------------------------------------
// Kernel 3: fused scores -> softmax (attn output) -> masked context -> pred.
// One block per batch b. 256 threads: tid = i2*8 + hq, i2 in [0,32), hq in [0,8).
// Thread owns rows i0=2*i2, i1=i0+1 and the h-slice {hq, hq+8, ..., hq+248}.
// Context accumulators live in registers (2 x 32). Softmax done redundantly in
// all hq lanes after shfl_xor reduction (no smem round trip).
// ---------------------------------------------------------------------------
__global__ void __launch_bounds__(256, 2) attn_kernel(
    const int* __restrict__ nine_idx,
    const float* __restrict__ W_lin,
    const float* __restrict__ b_lin,
    float* __restrict__ out)
{
    extern __shared__ float sm[];
    float* Hs  = sm;                    // 64 x 260 (padded)
    float* Gs  = Hs + 64 * 260;         // 9 x 260
    float* sWl = Gs + 9 * 260;          // 512
    int*   sidx = (int*)(sWl + 512);    // 9

    const int tid = threadIdx.x;
    const int b = blockIdx.x;
    const int i2 = tid >> 3;
    const int hq = tid & 7;
    const int i0 = i2 * 2;
    const int i1 = i0 + 1;

    if (tid < 9) sidx[tid] = nine_idx[b * 9 + tid];
    for (int m = tid; m < 512; m += 256) sWl[m] = W_lin[m];
#pragma unroll 4
    for (int m = tid; m < 64 * 256; m += 256) {
        int i = m >> 8, h = m & 255;
        Hs[i * 260 + h] = g_hs[((size_t)i * BB + b) * HH + h];
    }

    float acc0[32], acc1[32];
#pragma unroll
    for (int k = 0; k < 32; k++) { acc0[k] = 0.f; acc1[k] = 0.f; }
    __syncthreads();

    float* out_attn = out + (size_t)TT * BB;

    for (int j = 0; j < TT; j++) {
        // gather 9 rows: g[n][h] = hs[j, idx[b,n], h] (zeros row if idx == B)
#pragma unroll
        for (int n = 0; n < 9; n++) {
            int iv = sidx[n];
            float v = 0.f;
            if (iv < BB) v = g_hs[((size_t)j * BB + iv) * HH + tid];
            Gs[n * 260 + tid] = v;
        }
        __syncthreads();

        // scores: s[ii][n] = sum_h Hs[i][h] * Gs[n][h] (partial over h-slice)
        float s0[9], s1[9];
#pragma unroll
        for (int n = 0; n < 9; n++) { s0[n] = 0.f; s1[n] = 0.f; }
#pragma unroll 4
        for (int k = 0; k < 32; k++) {
            int h = hq + 8 * k;
            float x0 = Hs[i0 * 260 + h];
            float x1 = Hs[i1 * 260 + h];
#pragma unroll
            for (int n = 0; n < 9; n++) {
                float gv = Gs[n * 260 + h];
                s0[n] += x0 * gv;
                s1[n] += x1 * gv;
            }
        }
        // reduce the 8 hq-partials (lane bits 0..2)
#pragma unroll
        for (int n = 0; n < 9; n++) {
            float v0 = s0[n], v1 = s1[n];
            v0 += __shfl_xor_sync(0xffffffffu, v0, 1);
            v0 += __shfl_xor_sync(0xffffffffu, v0, 2);
            v0 += __shfl_xor_sync(0xffffffffu, v0, 4);
            v1 += __shfl_xor_sync(0xffffffffu, v1, 1);
            v1 += __shfl_xor_sync(0xffffffffu, v1, 2);
            v1 += __shfl_xor_sync(0xffffffffu, v1, 4);
            s0[n] = v0; s1[n] = v1;
        }
        // softmax over n (computed redundantly in every lane; values identical)
        float m0 = s0[0], m1 = s1[0];
#pragma unroll
        for (int n = 1; n < 9; n++) { m0 = fmaxf(m0, s0[n]); m1 = fmaxf(m1, s1[n]); }
        float sum0 = 0.f, sum1 = 0.f;
#pragma unroll
        for (int n = 0; n < 9; n++) {
            s0[n] = __expf(s0[n] - m0); sum0 += s0[n];
            s1[n] = __expf(s1[n] - m1); sum1 += s1[n];
        }
        float r0 = 1.f / sum0, r1 = 1.f / sum1;
#pragma unroll
        for (int n = 0; n < 9; n++) { s0[n] *= r0; s1[n] *= r1; }

        if (hq == 0) {
            size_t base0 = (((size_t)(i0 * TT + j)) * BB + b) * 9;
            size_t base1 = (((size_t)(i1 * TT + j)) * BB + b) * 9;
#pragma unroll
            for (int n = 0; n < 9; n++) {
                out_attn[base0 + n] = s0[n];
                out_attn[base1 + n] = s1[n];
            }
        }

        // masked context accumulation: only j < i contributes
        if (j < i1) {
            const bool d0 = (j < i0);
#pragma unroll
            for (int n = 0; n < 9; n++) {
                float pv0 = d0 ? s0[n] : 0.f;
                float pv1 = s1[n];
                const float* gp = Gs + n * 260 + hq;
#pragma unroll 8
                for (int k = 0; k < 32; k++) {
                    float gv = gp[8 * k];
                    acc0[k] += pv0 * gv;
                    acc1[k] += pv1 * gv;
                }
            }
        }
        __syncthreads();
    }

    // pred[i,b] = relu([c_i, hs_i] . W_lin + b_lin);  c_0 = hs_0, c_i = acc (i>0)
    const float bl = b_lin[0];
    float t0 = 0.f, t1 = 0.f;
    if (i0 == 0) {
#pragma unroll
        for (int k = 0; k < 32; k++) {
            int h = hq + 8 * k;
            t0 += Hs[h] * sWl[h];
        }
    } else {
#pragma unroll
        for (int k = 0; k < 32; k++) t0 += acc0[k] * sWl[hq + 8 * k];
    }
#pragma unroll
    for (int k = 0; k < 32; k++) t1 += acc1[k] * sWl[hq + 8 * k];
#pragma unroll
    for (int k = 0; k < 32; k++) {
        int h = hq + 8 * k;
        t0 += Hs[i0 * 260 + h] * sWl[256 + h];
        t1 += Hs[i1 * 260 + h] * sWl[256 + h];
    }
    t0 += __shfl_xor_sync(0xffffffffu, t0, 1);
    t0 += __shfl_xor_sync(0xffffffffu, t0, 2);
    t0 += __shfl_xor_sync(0xffffffffu, t0, 4);
    t1 += __shfl_xor_sync(0xffffffffu, t1, 1);
    t1 += __shfl_xor_sync(0xffffffffu, t1, 2);
    t1 += __shfl_xor_sync(0xffffffffu, t1, 4);
    if (hq == 0) {
        out[(size_t)i0 * BB + b] = fmaxf(t0 + bl, 0.f);
        out[(size_t)i1 * BB + b] = fmaxf(t1 + bl, 0.f);
    }
}

// ---------------------------------------------------------------------------
extern "C" void kernel_launch(void* const* d_in, const int* in_sizes, int n_in,
                              void* d_out, int out_size)
{
    const float* data  = (const float*)d_in[0];
    const int*   nidx  = (const int*)d_in[1];
    /* d_in[2] = haven_flag (always 0, branch unused) */
    const float* h0    = (const float*)d_in[3];
    const float* W_ih  = (const float*)d_in[4];
    const float* W_hh  = (const float*)d_in[5];
    const float* b_ih  = (const float*)d_in[6];
    const float* b_hh  = (const float*)d_in[7];
    const float* W_lin = (const float*)d_in[8];
    const float* b_lin = (const float*)d_in[9];
    float* out = (float*)d_out;

    (void)in_sizes; (void)n_in; (void)out_size;

    // 1) xW + biases into g_hs
    xw_kernel<<<1024, 256>>>(data, W_ih, b_ih, b_hh);

    // 2) recurrent scan, in place
    const int rnn_smem = (256 * 129 + 16 * 257) * (int)sizeof(float);
    cudaFuncSetAttribute(rnn_step_kernel,
                         cudaFuncAttributeMaxDynamicSharedMemorySize, rnn_smem);
    for (int t = 0; t < TT; t++) {
        rnn_step_kernel<<<128, 256, rnn_smem>>>(t, h0, W_hh);
    }

    // 3) fused attention + head
    const int attn_smem = (64 * 260 + 9 * 260 + 512) * (int)sizeof(float) + 64;
    cudaFuncSetAttribute(attn_kernel,
                         cudaFuncAttributeMaxDynamicSharedMemorySize, attn_smem);
    attn_kernel<<<1024, 256, attn_smem>>>(nidx, W_lin, b_lin, out);
}

// round 3
// speedup vs baseline: 1.1803x; 1.1803x over previous
#include <cuda_runtime.h>

#define TT 64
#define BB 1024
#define II 64
#define HH 256

// Scratch: hs[t][b][h] — first holds xW+biases, then overwritten in-place by the scan.
__device__ float g_hs[(size_t)TT * BB * HH];

// ---------------------------------------------------------------------------
// Kernel 1: g_hs[t,b,h] = data[t,b,:] . W_ih[h,:] + b_ih[h] + b_hh[h]
// ---------------------------------------------------------------------------
__global__ void __launch_bounds__(256) xw_kernel(
    const float* __restrict__ data,
    const float* __restrict__ W_ih,
    const float* __restrict__ b_ih,
    const float* __restrict__ b_hh)
{
    __shared__ float sX[256];  // 4 rows x 64 inputs
    const int tid = threadIdx.x;
    const long r0 = (long)blockIdx.x * 64;  // 64 (t,b)-rows per block

    float w[64];
    const float4* W4 = reinterpret_cast<const float4*>(W_ih) + tid * 16;
#pragma unroll
    for (int c = 0; c < 16; c++) {
        float4 v = W4[c];
        w[4*c+0] = v.x; w[4*c+1] = v.y; w[4*c+2] = v.z; w[4*c+3] = v.w;
    }
    const float bsum = b_ih[tid] + b_hh[tid];

    for (int rg = 0; rg < 16; rg++) {
        __syncthreads();
        sX[tid] = data[r0 * II + rg * 256 + tid];
        __syncthreads();
        float a0 = bsum, a1 = bsum, a2 = bsum, a3 = bsum;
        const float4* X4 = reinterpret_cast<const float4*>(sX);
#pragma unroll
        for (int c = 0; c < 16; c++) {
            float4 x;
            x = X4[c];      a0 += x.x*w[4*c] + x.y*w[4*c+1] + x.z*w[4*c+2] + x.w*w[4*c+3];
            x = X4[16+c];   a1 += x.x*w[4*c] + x.y*w[4*c+1] + x.z*w[4*c+2] + x.w*w[4*c+3];
            x = X4[32+c];   a2 += x.x*w[4*c] + x.y*w[4*c+1] + x.z*w[4*c+2] + x.w*w[4*c+3];
            x = X4[48+c];   a3 += x.x*w[4*c] + x.y*w[4*c+1] + x.z*w[4*c+2] + x.w*w[4*c+3];
        }
        long r = r0 + rg * 4;
        g_hs[(r+0)*HH + tid] = a0;
        g_hs[(r+1)*HH + tid] = a1;
        g_hs[(r+2)*HH + tid] = a2;
        g_hs[(r+3)*HH + tid] = a3;
    }
}

// ---------------------------------------------------------------------------
// Kernel 2: persistent RNN scan. The recurrence is independent per batch, so
// each block owns 8 batches for all 64 steps. h_prev lives in double-buffered
// smem (broadcast reads); W_hh is streamed per-row-per-thread through L1
// (256 KB, L1-resident after the first step). One barrier per step.
// 128 blocks x 512 threads: g = tid>>8 picks batches b0+4g..+3, h = tid&255.
// ---------------------------------------------------------------------------
__global__ void __launch_bounds__(512) rnn_scan_kernel(
    const float* __restrict__ h0_in, const float* __restrict__ W_hh)
{
    __shared__ float hp[2][8][256];
    const int tid = threadIdx.x;
    const int g = tid >> 8;
    const int h = tid & 255;
    const int b0 = blockIdx.x * 8;
    const int bg = g * 4;

    for (int m = tid; m < 2048; m += 512) {
        int bb = m >> 8, k = m & 255;
        hp[0][bb][k] = h0_in[(size_t)(b0 + bb) * HH + k];
    }
    __syncthreads();

    const float4* W4 = reinterpret_cast<const float4*>(W_hh + (size_t)h * HH);

    for (int t = 0; t < TT; t++) {
        float* hs_t = g_hs + (size_t)t * BB * HH;
        const int rb = t & 1;

        float acc[4];
#pragma unroll
        for (int b = 0; b < 4; b++)
            acc[b] = hs_t[(size_t)(b0 + bg + b) * HH + h];

        const float4* x0 = reinterpret_cast<const float4*>(&hp[rb][bg + 0][0]);
        const float4* x1 = reinterpret_cast<const float4*>(&hp[rb][bg + 1][0]);
        const float4* x2 = reinterpret_cast<const float4*>(&hp[rb][bg + 2][0]);
        const float4* x3 = reinterpret_cast<const float4*>(&hp[rb][bg + 3][0]);

#pragma unroll 8
        for (int k4 = 0; k4 < 64; k4++) {
            float4 w = W4[k4];
            float4 a = x0[k4];
            acc[0] += w.x*a.x + w.y*a.y + w.z*a.z + w.w*a.w;
            float4 b = x1[k4];
            acc[1] += w.x*b.x + w.y*b.y + w.z*b.z + w.w*b.w;
            float4 c = x2[k4];
            acc[2] += w.x*c.x + w.y*c.y + w.z*c.z + w.w*c.w;
            float4 d = x3[k4];
            acc[3] += w.x*d.x + w.y*d.y + w.z*d.z + w.w*d.w;
        }

#pragma unroll
        for (int b = 0; b < 4; b++) {
            float v = fmaxf(acc[b], 0.f);
            hs_t[(size_t)(b0 + bg + b) * HH + h] = v;
            hp[rb ^ 1][bg + b][h] = v;
        }
        __syncthreads();
    }
}

// ---------------------------------------------------------------------------
// Kernel 3: fused scores -> softmax -> masked context -> pred.
// One block per batch b, 256 threads: tid = i4*16 + hq.
// Thread owns i in {4*i4..4*i4+3} and h-slice {hq+16q, q=0..15}.
// Hs slice cached in registers (loaded once). Gather for j+1 prefetched into
// registers while computing j (double-buffered smem Gs, one barrier per j).
// ---------------------------------------------------------------------------
__global__ void __launch_bounds__(256, 1) attn_kernel(
    const int* __restrict__ nine_idx,
    const float* __restrict__ W_lin,
    const float* __restrict__ b_lin,
    float* __restrict__ out)
{
    __shared__ float Gs[2][9][256];
    __shared__ float sWl[512];
    __shared__ int sidx[9];

    const int tid = threadIdx.x;
    const int b = blockIdx.x;
    const int i4 = tid >> 4;      // 0..15
    const int hq = tid & 15;      // 0..15
    const int ibase = i4 * 4;

    if (tid < 9) sidx[tid] = nine_idx[b * 9 + tid];
    for (int m = tid; m < 512; m += 256) sWl[m] = W_lin[m];

    // register-cache this thread's Hs rows (4 i x 16 h)
    float hsr[4][16];
#pragma unroll
    for (int ii = 0; ii < 4; ii++) {
        const float* hpp = g_hs + ((size_t)(ibase + ii) * BB + b) * HH + hq;
#pragma unroll
        for (int q = 0; q < 16; q++) hsr[ii][q] = hpp[16 * q];
    }
    float acc[4][16];
#pragma unroll
    for (int ii = 0; ii < 4; ii++)
#pragma unroll
        for (int q = 0; q < 16; q++) acc[ii][q] = 0.f;

    const float bl = b_lin[0];
    __syncthreads();  // sidx ready

    // prefetch gather for j = 0
    float gr[9];
#pragma unroll
    for (int n = 0; n < 9; n++) {
        int iv = sidx[n];
        gr[n] = (iv < BB) ? g_hs[(size_t)iv * HH + tid] : 0.f;
    }

    float* out_attn = out + (size_t)TT * BB;

    for (int j = 0; j < TT; j++) {
        float* gbuf = &Gs[j & 1][0][0];
#pragma unroll
        for (int n = 0; n < 9; n++) gbuf[n * 256 + tid] = gr[n];
        __syncthreads();

        if (j < TT - 1) {
            const float* src = g_hs + (size_t)(j + 1) * BB * HH;
#pragma unroll
            for (int n = 0; n < 9; n++) {
                int iv = sidx[n];
                gr[n] = (iv < BB) ? src[(size_t)iv * HH + tid] : 0.f;
            }
        }

        // scores: s[ii][n] += hsr[ii][q] * g[n][hq+16q]
        float s[4][9];
#pragma unroll
        for (int ii = 0; ii < 4; ii++)
#pragma unroll
            for (int n = 0; n < 9; n++) s[ii][n] = 0.f;

#pragma unroll 4
        for (int q = 0; q < 16; q++) {
            float gv[9];
            const float* gp = gbuf + hq + 16 * q;
#pragma unroll
            for (int n = 0; n < 9; n++) gv[n] = gp[n * 256];
#pragma unroll
            for (int ii = 0; ii < 4; ii++) {
                float x = hsr[ii][q];
#pragma unroll
                for (int n = 0; n < 9; n++) s[ii][n] += x * gv[n];
            }
        }
        // reduce the 16 hq-partials (lane bits 0..3)
#pragma unroll
        for (int ii = 0; ii < 4; ii++) {
#pragma unroll
            for (int n = 0; n < 9; n++) {
                float v = s[ii][n];
                v += __shfl_xor_sync(0xffffffffu, v, 1);
                v += __shfl_xor_sync(0xffffffffu, v, 2);
                v += __shfl_xor_sync(0xffffffffu, v, 4);
                v += __shfl_xor_sync(0xffffffffu, v, 8);
                s[ii][n] = v;
            }
        }
        // softmax over n (redundant in all hq lanes; identical values)
#pragma unroll
        for (int ii = 0; ii < 4; ii++) {
            float m = s[ii][0];
#pragma unroll
            for (int n = 1; n < 9; n++) m = fmaxf(m, s[ii][n]);
            float sum = 0.f;
#pragma unroll
            for (int n = 0; n < 9; n++) { s[ii][n] = __expf(s[ii][n] - m); sum += s[ii][n]; }
            float r = 1.f / sum;
#pragma unroll
            for (int n = 0; n < 9; n++) s[ii][n] *= r;
        }

        // write attn: lanes hq<9 each write one n for all 4 i (coalesced 9-clump)
        if (hq < 9) {
#pragma unroll
            for (int ii = 0; ii < 4; ii++) {
                size_t base = (((size_t)((ibase + ii) * TT + j)) * BB + b) * 9 + hq;
                out_attn[base] = s[ii][hq];
            }
        }

        // masked context: only j < i contributes
        if (j < ibase + 3) {
#pragma unroll 4
            for (int q = 0; q < 16; q++) {
                float gv[9];
                const float* gp = gbuf + hq + 16 * q;
#pragma unroll
                for (int n = 0; n < 9; n++) gv[n] = gp[n * 256];
#pragma unroll
                for (int ii = 0; ii < 4; ii++) {
                    if (j < ibase + ii) {
#pragma unroll
                        for (int n = 0; n < 9; n++)
                            acc[ii][q] += s[ii][n] * gv[n];
                    }
                }
            }
        }
    }

    // head: pred[i,b] = relu([c_i, hs_i] . W_lin + b_lin); c_0 = hs_0
    float res[4];
#pragma unroll
    for (int ii = 0; ii < 4; ii++) {
        float t = 0.f;
        const bool zero_row = (ibase + ii == 0);
#pragma unroll
        for (int q = 0; q < 16; q++) {
            int hh = hq + 16 * q;
            float c = zero_row ? hsr[0][q] : acc[ii][q];
            t += c * sWl[hh] + hsr[ii][q] * sWl[256 + hh];
        }
        t += __shfl_xor_sync(0xffffffffu, t, 1);
        t += __shfl_xor_sync(0xffffffffu, t, 2);
        t += __shfl_xor_sync(0xffffffffu, t, 4);
        t += __shfl_xor_sync(0xffffffffu, t, 8);
        res[ii] = t;
    }
    if (hq == 0) {
#pragma unroll
        for (int ii = 0; ii < 4; ii++)
            out[(size_t)(ibase + ii) * BB + b] = fmaxf(res[ii] + bl, 0.f);
    }
}

// ---------------------------------------------------------------------------
extern "C" void kernel_launch(void* const* d_in, const int* in_sizes, int n_in,
                              void* d_out, int out_size)
{
    const float* data  = (const float*)d_in[0];
    const int*   nidx  = (const int*)d_in[1];
    /* d_in[2] = haven_flag (always 0, branch unused) */
    const float* h0    = (const float*)d_in[3];
    const float* W_ih  = (const float*)d_in[4];
    const float* W_hh  = (const float*)d_in[5];
    const float* b_ih  = (const float*)d_in[6];
    const float* b_hh  = (const float*)d_in[7];
    const float* W_lin = (const float*)d_in[8];
    const float* b_lin = (const float*)d_in[9];
    float* out = (float*)d_out;

    (void)in_sizes; (void)n_in; (void)out_size;

    xw_kernel<<<1024, 256>>>(data, W_ih, b_ih, b_hh);
    rnn_scan_kernel<<<128, 512>>>(h0, W_hh);
    attn_kernel<<<1024, 256>>>(nidx, W_lin, b_lin, out);
}

// round 4
// speedup vs baseline: 1.4807x; 1.2545x over previous
#include <cuda_runtime.h>

#define TT 64
#define BB 1024
#define II 64
#define HH 256

// Scratch: hs[t][b][h] — first holds xW+biases, then overwritten in-place by the scan.
__device__ float g_hs[(size_t)TT * BB * HH];

// ---------------------------------------------------------------------------
// Kernel 1: g_hs[t,b,h] = data[t,b,:] . W_ih[h,:] + b_ih[h] + b_hh[h]
// ---------------------------------------------------------------------------
__global__ void __launch_bounds__(256) xw_kernel(
    const float* __restrict__ data,
    const float* __restrict__ W_ih,
    const float* __restrict__ b_ih,
    const float* __restrict__ b_hh)
{
    __shared__ float sX[256];  // 4 rows x 64 inputs
    const int tid = threadIdx.x;
    const long r0 = (long)blockIdx.x * 64;  // 64 (t,b)-rows per block

    float w[64];
    const float4* W4 = reinterpret_cast<const float4*>(W_ih) + tid * 16;
#pragma unroll
    for (int c = 0; c < 16; c++) {
        float4 v = W4[c];
        w[4*c+0] = v.x; w[4*c+1] = v.y; w[4*c+2] = v.z; w[4*c+3] = v.w;
    }
    const float bsum = b_ih[tid] + b_hh[tid];

    for (int rg = 0; rg < 16; rg++) {
        __syncthreads();
        sX[tid] = data[r0 * II + rg * 256 + tid];
        __syncthreads();
        float a0 = bsum, a1 = bsum, a2 = bsum, a3 = bsum;
        const float4* X4 = reinterpret_cast<const float4*>(sX);
#pragma unroll
        for (int c = 0; c < 16; c++) {
            float4 x;
            x = X4[c];      a0 += x.x*w[4*c] + x.y*w[4*c+1] + x.z*w[4*c+2] + x.w*w[4*c+3];
            x = X4[16+c];   a1 += x.x*w[4*c] + x.y*w[4*c+1] + x.z*w[4*c+2] + x.w*w[4*c+3];
            x = X4[32+c];   a2 += x.x*w[4*c] + x.y*w[4*c+1] + x.z*w[4*c+2] + x.w*w[4*c+3];
            x = X4[48+c];   a3 += x.x*w[4*c] + x.y*w[4*c+1] + x.z*w[4*c+2] + x.w*w[4*c+3];
        }
        long r = r0 + rg * 4;
        g_hs[(r+0)*HH + tid] = a0;
        g_hs[(r+1)*HH + tid] = a1;
        g_hs[(r+2)*HH + tid] = a2;
        g_hs[(r+3)*HH + tid] = a3;
    }
}

// ---------------------------------------------------------------------------
// Kernel 2: persistent RNN scan. Each block owns 8 batches for all 64 steps.
// h_prev double-buffered in smem (broadcast reads); W_hh streamed via L1/L2.
// ---------------------------------------------------------------------------
__global__ void __launch_bounds__(512) rnn_scan_kernel(
    const float* __restrict__ h0_in, const float* __restrict__ W_hh)
{
    __shared__ float hp[2][8][256];
    const int tid = threadIdx.x;
    const int g = tid >> 8;
    const int h = tid & 255;
    const int b0 = blockIdx.x * 8;
    const int bg = g * 4;

    for (int m = tid; m < 2048; m += 512) {
        int bb = m >> 8, k = m & 255;
        hp[0][bb][k] = h0_in[(size_t)(b0 + bb) * HH + k];
    }
    __syncthreads();

    const float4* W4 = reinterpret_cast<const float4*>(W_hh + (size_t)h * HH);

    for (int t = 0; t < TT; t++) {
        float* hs_t = g_hs + (size_t)t * BB * HH;
        const int rb = t & 1;

        float acc[4];
#pragma unroll
        for (int b = 0; b < 4; b++)
            acc[b] = hs_t[(size_t)(b0 + bg + b) * HH + h];

        const float4* x0 = reinterpret_cast<const float4*>(&hp[rb][bg + 0][0]);
        const float4* x1 = reinterpret_cast<const float4*>(&hp[rb][bg + 1][0]);
        const float4* x2 = reinterpret_cast<const float4*>(&hp[rb][bg + 2][0]);
        const float4* x3 = reinterpret_cast<const float4*>(&hp[rb][bg + 3][0]);

#pragma unroll 8
        for (int k4 = 0; k4 < 64; k4++) {
            float4 w = W4[k4];
            float4 a = x0[k4];
            acc[0] += w.x*a.x + w.y*a.y + w.z*a.z + w.w*a.w;
            float4 b = x1[k4];
            acc[1] += w.x*b.x + w.y*b.y + w.z*b.z + w.w*b.w;
            float4 c = x2[k4];
            acc[2] += w.x*c.x + w.y*c.y + w.z*c.z + w.w*c.w;
            float4 d = x3[k4];
            acc[3] += w.x*d.x + w.y*d.y + w.z*d.z + w.w*d.w;
        }

#pragma unroll
        for (int b = 0; b < 4; b++) {
            float v = fmaxf(acc[b], 0.f);
            hs_t[(size_t)(b0 + bg + b) * HH + h] = v;
            hp[rb ^ 1][bg + b][h] = v;
        }
        __syncthreads();
    }
}

// ---------------------------------------------------------------------------
// Kernel 3: fused scores -> softmax -> masked context -> pred.
// One block per batch b, 512 threads: tid = iq*16 + hq, iq in [0,32), hq in [0,16).
// Thread owns rows i0=2*iq, i1=i0+1 and h-slice {hq+16q, q=0..15}.
// Hs slice cached in registers; 2x16 context accumulators in registers.
// Gather for j+1 prefetched into registers (5 rows per block-half) while
// computing j; double-buffered smem Gs, one barrier per j.
// ~110 regs/thread -> no spills, 16 warps/SM.
// ---------------------------------------------------------------------------
__global__ void __launch_bounds__(512, 1) attn_kernel(
    const int* __restrict__ nine_idx,
    const float* __restrict__ W_lin,
    const float* __restrict__ b_lin,
    float* __restrict__ out)
{
    __shared__ float Gs[2][9][257];
    __shared__ float sWl[512];
    __shared__ int sidx[9];

    const int tid = threadIdx.x;
    const int b = blockIdx.x;
    const int iq = tid >> 4;      // 0..31
    const int hq = tid & 15;      // 0..15
    const int i0 = iq * 2;
    const int i1 = i0 + 1;
    const int h = tid & 255;      // gather lane
    const int nb = (tid >> 8) * 4; // 0 or 4: this half loads n = nb..nb+4

    if (tid < 9) sidx[tid] = nine_idx[b * 9 + tid];
    if (tid < 512) sWl[tid] = W_lin[tid];
    __syncthreads();  // sidx ready

    // register-cache this thread's Hs rows (2 i x 16 h)
    float hsr[2][16];
#pragma unroll
    for (int ii = 0; ii < 2; ii++) {
        const float* hpp = g_hs + ((size_t)(i0 + ii) * BB + b) * HH + hq;
#pragma unroll
        for (int q = 0; q < 16; q++) hsr[ii][q] = hpp[16 * q];
    }
    float acc[2][16];
#pragma unroll
    for (int ii = 0; ii < 2; ii++)
#pragma unroll
        for (int q = 0; q < 16; q++) acc[ii][q] = 0.f;

    const float bl = b_lin[0];

    // prefetch gather for j = 0 (each block-half loads 5 of the 9 rows; n=4 dup)
    float gr[5];
#pragma unroll
    for (int k = 0; k < 5; k++) {
        int iv = sidx[nb + k];
        gr[k] = (iv < BB) ? g_hs[(size_t)iv * HH + h] : 0.f;
    }

    float* out_attn = out + (size_t)TT * BB;

    for (int j = 0; j < TT; j++) {
        float* gbuf = &Gs[j & 1][0][0];
#pragma unroll
        for (int k = 0; k < 5; k++) gbuf[(nb + k) * 257 + h] = gr[k];
        __syncthreads();

        if (j < TT - 1) {
            const float* src = g_hs + (size_t)(j + 1) * BB * HH;
#pragma unroll
            for (int k = 0; k < 5; k++) {
                int iv = sidx[nb + k];
                gr[k] = (iv < BB) ? src[(size_t)iv * HH + h] : 0.f;
            }
        }

        // scores: s[ii][n] += hsr[ii][q] * g[n][hq+16q]
        float s[2][9];
#pragma unroll
        for (int ii = 0; ii < 2; ii++)
#pragma unroll
            for (int n = 0; n < 9; n++) s[ii][n] = 0.f;

#pragma unroll 4
        for (int q = 0; q < 16; q++) {
            const float* gp = gbuf + hq + 16 * q;
            float x0 = hsr[0][q];
            float x1 = hsr[1][q];
#pragma unroll
            for (int n = 0; n < 9; n++) {
                float gv = gp[n * 257];
                s[0][n] += x0 * gv;
                s[1][n] += x1 * gv;
            }
        }
        // reduce the 16 hq-partials (lane bits 0..3)
#pragma unroll
        for (int ii = 0; ii < 2; ii++) {
#pragma unroll
            for (int n = 0; n < 9; n++) {
                float v = s[ii][n];
                v += __shfl_xor_sync(0xffffffffu, v, 1);
                v += __shfl_xor_sync(0xffffffffu, v, 2);
                v += __shfl_xor_sync(0xffffffffu, v, 4);
                v += __shfl_xor_sync(0xffffffffu, v, 8);
                s[ii][n] = v;
            }
        }
        // softmax over n (redundant in all hq lanes; identical values)
#pragma unroll
        for (int ii = 0; ii < 2; ii++) {
            float m = s[ii][0];
#pragma unroll
            for (int n = 1; n < 9; n++) m = fmaxf(m, s[ii][n]);
            float sum = 0.f;
#pragma unroll
            for (int n = 0; n < 9; n++) { s[ii][n] = __expf(s[ii][n] - m); sum += s[ii][n]; }
            float r = 1.f / sum;
#pragma unroll
            for (int n = 0; n < 9; n++) s[ii][n] *= r;
        }

        // write attn: lanes hq<9 each write one n for both i (coalesced 9-clump)
        if (hq < 9) {
#pragma unroll
            for (int ii = 0; ii < 2; ii++) {
                size_t base = (((size_t)((i0 + ii) * TT + j)) * BB + b) * 9 + hq;
                out_attn[base] = s[ii][hq];
            }
        }

        // masked context: only j < i contributes
        if (j < i1) {
            const bool both = (j < i0);
#pragma unroll 4
            for (int q = 0; q < 16; q++) {
                const float* gp = gbuf + hq + 16 * q;
                float a0 = 0.f, a1 = 0.f;
#pragma unroll
                for (int n = 0; n < 9; n++) {
                    float gv = gp[n * 257];
                    a0 += s[0][n] * gv;
                    a1 += s[1][n] * gv;
                }
                if (both) acc[0][q] += a0;
                acc[1][q] += a1;
            }
        }
        __syncthreads();
    }

    // head: pred[i,b] = relu([c_i, hs_i] . W_lin + b_lin); c_0 = hs_0
    float res[2];
#pragma unroll
    for (int ii = 0; ii < 2; ii++) {
        float t = 0.f;
        const bool zero_row = (i0 + ii == 0);
#pragma unroll
        for (int q = 0; q < 16; q++) {
            int hh = hq + 16 * q;
            float c = zero_row ? hsr[0][q] : acc[ii][q];
            t += c * sWl[hh] + hsr[ii][q] * sWl[256 + hh];
        }
        t += __shfl_xor_sync(0xffffffffu, t, 1);
        t += __shfl_xor_sync(0xffffffffu, t, 2);
        t += __shfl_xor_sync(0xffffffffu, t, 4);
        t += __shfl_xor_sync(0xffffffffu, t, 8);
        res[ii] = t;
    }
    if (hq == 0) {
#pragma unroll
        for (int ii = 0; ii < 2; ii++)
            out[(size_t)(i0 + ii) * BB + b] = fmaxf(res[ii] + bl, 0.f);
    }
}

// ---------------------------------------------------------------------------
extern "C" void kernel_launch(void* const* d_in, const int* in_sizes, int n_in,
                              void* d_out, int out_size)
{
    const float* data  = (const float*)d_in[0];
    const int*   nidx  = (const int*)d_in[1];
    /* d_in[2] = haven_flag (always 0, branch unused) */
    const float* h0    = (const float*)d_in[3];
    const float* W_ih  = (const float*)d_in[4];
    const float* W_hh  = (const float*)d_in[5];
    const float* b_ih  = (const float*)d_in[6];
    const float* b_hh  = (const float*)d_in[7];
    const float* W_lin = (const float*)d_in[8];
    const float* b_lin = (const float*)d_in[9];
    float* out = (float*)d_out;

    (void)in_sizes; (void)n_in; (void)out_size;

    xw_kernel<<<1024, 256>>>(data, W_ih, b_ih, b_hh);
    rnn_scan_kernel<<<128, 512>>>(h0, W_hh);
    attn_kernel<<<1024, 512>>>(nidx, W_lin, b_lin, out);
}